// round 12
// baseline (speedup 1.0000x reference)
#include <cuda_runtime.h>
#include <cuda_fp16.h>
#include <math.h>
#include <stdint.h>

#define TPB 128
#define BM  128
#define BN  64
#define DHD 64
#define K2E 0.1803368801f   // log2(e)/8

#define BH_MAX 32
#define N_MAX  2048
#define MAXE   (BH_MAX * N_MAX * DHD)

// stage: 128 rows x 128B (rows 0-63 = K, 64-127 = V); 3 stages
#define STG 16384
#define SMEM_TOTAL (3 * STG)

__device__ __align__(16) __half   g_qh[MAXE];
__device__ __align__(16) __half   g_kv[2 * MAXE];            // [bh][t][128 rows][64 halves]
__device__ float    g_qn2[BH_MAX * N_MAX];
__device__ float    g_maxk2[BH_MAX];
__device__ __align__(16) uint32_t g_mask[N_MAX * N_MAX / 2]; // [row][t][qd][nb] AND-words

// ---------------- helpers ----------------
__device__ __forceinline__ uint32_t smem_u32(const void* p) {
    uint32_t a;
    asm("{ .reg .u64 t; cvta.to.shared.u64 t, %1; cvt.u32.u64 %0, t; }" : "=r"(a) : "l"(p));
    return a;
}
__device__ __forceinline__ void cp16(uint32_t dst, const void* src) {
    asm volatile("cp.async.cg.shared.global [%0], [%1], 16;" :: "r"(dst), "l"(src));
}
#define CP_COMMIT() asm volatile("cp.async.commit_group;" ::: "memory")
#define CP_WAIT0()  asm volatile("cp.async.wait_group 0;" ::: "memory")
#define CP_WAIT1()  asm volatile("cp.async.wait_group 1;" ::: "memory")

__device__ __forceinline__ void ldsm_x4(uint32_t* r, uint32_t a) {
    asm volatile("ldmatrix.sync.aligned.m8n8.x4.shared.b16 {%0,%1,%2,%3}, [%4];"
                 : "=r"(r[0]), "=r"(r[1]), "=r"(r[2]), "=r"(r[3]) : "r"(a));
}
__device__ __forceinline__ void ldsm_x4t(uint32_t* r, uint32_t a) {
    asm volatile("ldmatrix.sync.aligned.m8n8.x4.trans.shared.b16 {%0,%1,%2,%3}, [%4];"
                 : "=r"(r[0]), "=r"(r[1]), "=r"(r[2]), "=r"(r[3]) : "r"(a));
}
__device__ __forceinline__ void mma16816(float* c, const uint32_t* a, uint32_t b0, uint32_t b1) {
    asm volatile("mma.sync.aligned.m16n8k16.row.col.f32.f16.f16.f32 "
                 "{%0,%1,%2,%3}, {%4,%5,%6,%7}, {%8,%9}, {%0,%1,%2,%3};"
                 : "+f"(c[0]), "+f"(c[1]), "+f"(c[2]), "+f"(c[3])
                 : "r"(a[0]), "r"(a[1]), "r"(a[2]), "r"(a[3]), "r"(b0), "r"(b1));
}
__device__ __forceinline__ float ex2(float x) {
    float r; asm("ex2.approx.f32 %0, %1;" : "=f"(r) : "f"(x)); return r;
}
__device__ __forceinline__ uint32_t h2bits(__half2 h) { return *(uint32_t*)&h; }
__device__ __forceinline__ uint32_t swzo(int row, int colb) {
    return (uint32_t)((row * 128 + colb) ^ ((row & 7) << 4));
}

// ---------------- merged prepass (unchanged from R11) ----------------
__global__ void prepass_kernel(const int4* __restrict__ adj,
                               const float4* __restrict__ Q,
                               const float4* __restrict__ K,
                               const float4* __restrict__ V,
                               int N, int adjB)
{
    if (blockIdx.x < adjB) {
        const int g   = blockIdx.x * 256 + threadIdx.x;
        const int row = g >> 6, seg = g & 63;
        const int t   = seg >> 1, h = seg & 1;
        const int4* bp = adj + (size_t)row * (N >> 2) + t * 16 + h * 8;
        int4 a[8];
        #pragma unroll
        for (int i = 0; i < 8; i++) a[i] = bp[i];
        uint32_t w[4][4];
        #pragma unroll
        for (int i = 0; i < 4; i++) {
            int4 lo = a[2 * i], hi = a[2 * i + 1];
            w[0][i] = (lo.x > 0 ? 0xFFFFu : 0u) | (lo.y > 0 ? 0xFFFF0000u : 0u);
            w[1][i] = (lo.z > 0 ? 0xFFFFu : 0u) | (lo.w > 0 ? 0xFFFF0000u : 0u);
            w[2][i] = (hi.x > 0 ? 0xFFFFu : 0u) | (hi.y > 0 ? 0xFFFF0000u : 0u);
            w[3][i] = (hi.z > 0 ? 0xFFFFu : 0u) | (hi.w > 0 ? 0xFFFF0000u : 0u);
        }
        const int nT = N >> 6;
        #pragma unroll
        for (int qd = 0; qd < 4; qd++)
            ((uint4*)g_mask)[(((size_t)row * nT + t) * 4 + qd) * 2 + h] =
                make_uint4(w[qd][0], w[qd][1], w[qd][2], w[qd][3]);
        return;
    }
    __shared__ float skn[16];
    const int idx = (blockIdx.x - adjB) * 256 + threadIdx.x;
    float4 q = Q[idx], k = K[idx], v = V[idx];

    ((uint2*)g_qh)[idx] = make_uint2(h2bits(__floats2half2_rn(q.x, q.y)),
                                     h2bits(__floats2half2_rn(q.z, q.w)));
    const int rl  = idx >> 4;
    const int bh  = rl / N;
    const int row = rl - bh * N;
    const int t   = row >> 6, r = row & 63, c4 = idx & 15;
    const size_t u2 = ((size_t)(bh * (N >> 6) + t) * 128 + r) * 16 + c4;
    ((uint2*)g_kv)[u2]        = make_uint2(h2bits(__floats2half2_rn(k.x, k.y)),
                                           h2bits(__floats2half2_rn(k.z, k.w)));
    ((uint2*)g_kv)[u2 + 1024] = make_uint2(h2bits(__floats2half2_rn(v.x, v.y)),
                                           h2bits(__floats2half2_rn(v.z, v.w)));

    float qn2 = q.x * q.x + q.y * q.y + q.z * q.z + q.w * q.w;
    float kn2 = k.x * k.x + k.y * k.y + k.z * k.z + k.w * k.w;
    #pragma unroll
    for (int o = 8; o; o >>= 1) {
        qn2 += __shfl_xor_sync(0xffffffffu, qn2, o);
        kn2 += __shfl_xor_sync(0xffffffffu, kn2, o);
    }
    if ((threadIdx.x & 15) == 0) {
        g_qn2[idx >> 4] = qn2;
        skn[threadIdx.x >> 4] = kn2;
    }
    __syncthreads();
    if (threadIdx.x == 0) {
        float m = skn[0];
        #pragma unroll
        for (int i = 1; i < 16; i++) m = fmaxf(m, skn[i]);
        atomicMax((int*)&g_maxk2[bh], __float_as_int(m));
    }
}

// ---------------- main kernel: warp-m = 32 (BM = 128) ----------------
__global__ __launch_bounds__(TPB, 2)
void gat_hmma8_kernel(float* __restrict__ out, int N)
{
    extern __shared__ char sm[];
    const uint32_t smb = smem_u32(sm);

    const int tid  = threadIdx.x;
    const int wid  = tid >> 5;
    const int lane = tid & 31;
    const int mg   = lane >> 3;
    const int mr   = lane & 7;
    const int r4   = lane >> 2;
    const int qd   = lane & 3;

    const int bh   = blockIdx.y;
    const int row0 = blockIdx.x * BM;
    const int nT   = N / BN;

    // ---- Q fragments via stage0 (128 rows x 128B = 16KB) ----
    {
        const char* qhB = (const char*)g_qh + ((size_t)bh * N + row0) * (DHD * 2);
        #pragma unroll
        for (int i = 0; i < 8; i++) {
            int idx = tid + i * TPB;
            int row = idx >> 3, c = idx & 7;
            cp16(smb + swzo(row, c * 16), qhB + row * 128 + c * 16);
        }
        CP_COMMIT(); CP_WAIT0();
        __syncthreads();
    }
    uint32_t qh[2][4][4];
    #pragma unroll
    for (int mt = 0; mt < 2; mt++) {
        const int arow = wid * 32 + mt * 16 + ((mg & 1) << 3) + mr;
        #pragma unroll
        for (int kb = 0; kb < 4; kb++)
            ldsm_x4(qh[mt][kb], smb + swzo(arow, kb * 32 + ((mg >> 1) << 4)));
    }
    __syncthreads();

    // ---- per-row biases (4 row-groups), mask base, ones fragment ----
    const float mk2 = g_maxk2[bh];
    const int rowa  = row0 + wid * 32 + r4;
    const float sb00 = 14.0f - sqrtf(g_qn2[(size_t)bh * N + rowa]      * mk2) * K2E;
    const float sb01 = 14.0f - sqrtf(g_qn2[(size_t)bh * N + rowa +  8] * mk2) * K2E;
    const float sb10 = 14.0f - sqrtf(g_qn2[(size_t)bh * N + rowa + 16] * mk2) * K2E;
    const float sb11 = 14.0f - sqrtf(g_qn2[(size_t)bh * N + rowa + 24] * mk2) * K2E;
    const uint32_t* mp = g_mask + (size_t)rowa * nT * 32 + qd * 8;
    const size_t rstep = (size_t)8 * nT * 32;   // mask stride for +8 rows
    const uint32_t bo = (lane < 4) ? 0x3C003C00u : 0u;

    // ---- hoisted ldsm addresses (swizzle term thread-constant) ----
    const uint32_t mrx = (uint32_t)(mr << 4);
    uint32_t addrS[4], addrV[4];
    {
        uint32_t bS = smb + (uint32_t)((((mg >> 1) << 3) + mr) * 128);
        uint32_t bV = smb + 8192 + (uint32_t)((((mg & 1) << 3) + mr) * 128);
        #pragma unroll
        for (int k = 0; k < 4; k++) {
            addrS[k] = bS + ((uint32_t)(k * 32 + ((mg & 1) << 4)) ^ mrx);
            addrV[k] = bV + ((uint32_t)(k * 32 + ((mg >> 1) << 4)) ^ mrx);
        }
    }

    // ---- cp.async bases ----
    const uint32_t so0 = (uint32_t)((tid >> 3) * 128 + (((tid & 7) * 16) ^ (((tid >> 3) & 7) << 4)));
    const char* kvSrc = (const char*)g_kv + (size_t)bh * N * 256 + (tid >> 3) * 128 + (tid & 7) * 16;
    uint32_t cpDst = smb + STG + so0;
    int cpStage = 1;

    float o0[8][4], o1[8][4];
    #pragma unroll
    for (int i = 0; i < 8; i++)
        #pragma unroll
        for (int j = 0; j < 4; j++) { o0[i][j] = 0.f; o1[i][j] = 0.f; }
    float lf0[4] = {0.f, 0.f, 0.f, 0.f};
    float lf1[4] = {0.f, 0.f, 0.f, 0.f};

    // prefetch tile 0 -> stage 0
    #pragma unroll
    for (int i = 0; i < 8; i++) cp16(smb + so0 + i * 2048, kvSrc + i * 2048);
    CP_COMMIT();
    kvSrc += 16384;

    int st = 0;
    for (int t = 0; t < nT; t++) {
        if (t + 1 < nT) {
            #pragma unroll
            for (int i = 0; i < 8; i++) cp16(cpDst + i * 2048, kvSrc + i * 2048);
            CP_COMMIT(); CP_WAIT1();
            kvSrc += 16384;
            int d2 = (cpStage == 2) ? -2 * STG : STG;
            cpStage = (cpStage == 2) ? 0 : cpStage + 1;
            cpDst += d2;
        } else {
            CP_WAIT0();
        }
        __syncthreads();   // single barrier per tile (3-stage ring)

        // hoisted mask loads (4 row-groups x 8 words)
        const uint4 qa0 = *(const uint4*)(mp);
        const uint4 qb0 = *(const uint4*)(mp + 4);
        const uint4 qa1 = *(const uint4*)(mp + rstep);
        const uint4 qb1 = *(const uint4*)(mp + rstep + 4);
        const uint4 qa2 = *(const uint4*)(mp + 2 * rstep);
        const uint4 qb2 = *(const uint4*)(mp + 2 * rstep + 4);
        const uint4 qa3 = *(const uint4*)(mp + 3 * rstep);
        const uint4 qb3 = *(const uint4*)(mp + 3 * rstep + 4);
        mp += 32;

        // ---- S = Qh*Kh for both m-tiles (shared B fragments) ----
        float c0[8][4], c1[8][4];
        #pragma unroll
        for (int i = 0; i < 8; i++)
            #pragma unroll
            for (int j = 0; j < 4; j++) { c0[i][j] = 0.f; c1[i][j] = 0.f; }

        #pragma unroll
        for (int kb = 0; kb < 4; kb++) {
            #pragma unroll
            for (int j = 0; j < 4; j++) {
                uint32_t bhr[4];
                ldsm_x4(bhr, addrS[kb] + j * 2048);
                mma16816(c0[2 * j],     qh[0][kb], bhr[0], bhr[1]);
                mma16816(c0[2 * j + 1], qh[0][kb], bhr[2], bhr[3]);
                mma16816(c1[2 * j],     qh[1][kb], bhr[0], bhr[1]);
                mma16816(c1[2 * j + 1], qh[1][kb], bhr[2], bhr[3]);
            }
        }

        // ---- exp ----
        #pragma unroll
        for (int nb = 0; nb < 8; nb++) {
            c0[nb][0] = ex2(fmaf(c0[nb][0], K2E, sb00));
            c0[nb][1] = ex2(fmaf(c0[nb][1], K2E, sb00));
            c0[nb][2] = ex2(fmaf(c0[nb][2], K2E, sb01));
            c0[nb][3] = ex2(fmaf(c0[nb][3], K2E, sb01));
            c1[nb][0] = ex2(fmaf(c1[nb][0], K2E, sb10));
            c1[nb][1] = ex2(fmaf(c1[nb][1], K2E, sb10));
            c1[nb][2] = ex2(fmaf(c1[nb][2], K2E, sb11));
            c1[nb][3] = ex2(fmaf(c1[nb][3], K2E, sb11));
        }

        const uint32_t mA0[8] = {qa0.x, qa0.y, qa0.z, qa0.w, qb0.x, qb0.y, qb0.z, qb0.w};
        const uint32_t mB0[8] = {qa1.x, qa1.y, qa1.z, qa1.w, qb1.x, qb1.y, qb1.z, qb1.w};
        const uint32_t mA1[8] = {qa2.x, qa2.y, qa2.z, qa2.w, qb2.x, qb2.y, qb2.z, qb2.w};
        const uint32_t mB1[8] = {qa3.x, qa3.y, qa3.z, qa3.w, qb3.x, qb3.y, qb3.z, qb3.w};

        // ---- O += Ph*Vh, l += Ph*ones (shared V fragments) ----
        #pragma unroll
        for (int kb2 = 0; kb2 < 4; kb2++) {
            const int e = 2 * kb2, od = e + 1;
            uint32_t ph0[4], ph1[4];
            ph0[0] = h2bits(__floats2half2_rn(c0[e][0],  c0[e][1]))  & mA0[e];
            ph0[1] = h2bits(__floats2half2_rn(c0[e][2],  c0[e][3]))  & mB0[e];
            ph0[2] = h2bits(__floats2half2_rn(c0[od][0], c0[od][1])) & mA0[od];
            ph0[3] = h2bits(__floats2half2_rn(c0[od][2], c0[od][3])) & mB0[od];
            ph1[0] = h2bits(__floats2half2_rn(c1[e][0],  c1[e][1]))  & mA1[e];
            ph1[1] = h2bits(__floats2half2_rn(c1[e][2],  c1[e][3]))  & mB1[e];
            ph1[2] = h2bits(__floats2half2_rn(c1[od][0], c1[od][1])) & mA1[od];
            ph1[3] = h2bits(__floats2half2_rn(c1[od][2], c1[od][3])) & mB1[od];
            #pragma unroll
            for (int j = 0; j < 4; j++) {
                uint32_t vh4[4];
                ldsm_x4t(vh4, addrV[j] + kb2 * 2048);
                mma16816(o0[2 * j],     ph0, vh4[0], vh4[1]);
                mma16816(o0[2 * j + 1], ph0, vh4[2], vh4[3]);
                mma16816(o1[2 * j],     ph1, vh4[0], vh4[1]);
                mma16816(o1[2 * j + 1], ph1, vh4[2], vh4[3]);
            }
            mma16816(lf0, ph0, bo, bo);
            mma16816(lf1, ph1, bo, bo);
        }

        int d = (st == 2) ? -2 * STG : STG;
        st = (st == 2) ? 0 : st + 1;
        #pragma unroll
        for (int k = 0; k < 4; k++) { addrS[k] += d; addrV[k] += d; }
    }

    // ---- normalize + store ----
    const float l00 = __shfl_sync(0xffffffffu, lf0[0], lane & 28);
    const float l01 = __shfl_sync(0xffffffffu, lf0[2], lane & 28);
    const float l10 = __shfl_sync(0xffffffffu, lf1[0], lane & 28);
    const float l11 = __shfl_sync(0xffffffffu, lf1[2], lane & 28);
    const float i00 = 1.0f / l00, i01 = 1.0f / l01;
    const float i10 = 1.0f / l10, i11 = 1.0f / l11;

    float2* op = (float2*)out;
    const int orow0 = row0 + wid * 32 + r4;
    #pragma unroll
    for (int nb = 0; nb < 8; nb++) {
        const int d = nb * 8 + qd * 2;
        op[(((size_t)bh * N + orow0) * DHD + d) >> 1] =
            make_float2(o0[nb][0] * i00, o0[nb][1] * i00);
        op[(((size_t)bh * N + orow0 + 8) * DHD + d) >> 1] =
            make_float2(o0[nb][2] * i01, o0[nb][3] * i01);
        op[(((size_t)bh * N + orow0 + 16) * DHD + d) >> 1] =
            make_float2(o1[nb][0] * i10, o1[nb][1] * i10);
        op[(((size_t)bh * N + orow0 + 24) * DHD + d) >> 1] =
            make_float2(o1[nb][2] * i11, o1[nb][3] * i11);
    }
}

// ---------------- launcher ----------------
extern "C" void kernel_launch(void* const* d_in, const int* in_sizes, int n_in,
                              void* d_out, int out_size)
{
    const float* Q   = (const float*)d_in[0];
    const float* K   = (const float*)d_in[1];
    const float* V   = (const float*)d_in[2];
    const int*   adj = (const int*)d_in[3];
    float*       out = (float*)d_out;

    const int N  = (int)(sqrt((double)in_sizes[3]) + 0.5);
    const int BH = in_sizes[0] / (N * DHD);

    const int adjB = (N * N / 32) / 256;
    const int cvtB = (BH * N * DHD / 4) / 256;
    prepass_kernel<<<adjB + cvtB, 256>>>((const int4*)adj, (const float4*)Q,
                                         (const float4*)K, (const float4*)V, N, adjB);

    cudaFuncSetAttribute(gat_hmma8_kernel,
                         cudaFuncAttributeMaxDynamicSharedMemorySize, SMEM_TOTAL);
    dim3 grid(N / BM, BH);
    gat_hmma8_kernel<<<grid, TPB, SMEM_TOTAL>>>(out, N);
}

// round 13
// speedup vs baseline: 1.1073x; 1.1073x over previous
#include <cuda_runtime.h>
#include <cuda_fp16.h>
#include <math.h>
#include <stdint.h>

#define TPB 128
#define BM  64
#define BN  64
#define DHD 64
#define K2E 0.1803368801f   // log2(e)/8

#define BH_MAX 32
#define N_MAX  2048
#define MAXE   (BH_MAX * N_MAX * DHD)

// stage: 128 rows x 128B (rows 0-63 = K, 64-127 = V); 3 stages
#define STG 16384
#define SMEM_TOTAL (3 * STG)

__device__ __align__(16) __half   g_qh[MAXE];
__device__ __align__(16) __half   g_kv[2 * MAXE];            // [bh][t][128 rows][64 halves]
__device__ float    g_qn2[BH_MAX * N_MAX];
__device__ float    g_maxk2[BH_MAX];
__device__ __align__(16) uint32_t g_mask[N_MAX * N_MAX / 2]; // [row][t][qd][nb] AND-words

// ---------------- helpers ----------------
__device__ __forceinline__ uint32_t smem_u32(const void* p) {
    uint32_t a;
    asm("{ .reg .u64 t; cvta.to.shared.u64 t, %1; cvt.u32.u64 %0, t; }" : "=r"(a) : "l"(p));
    return a;
}
__device__ __forceinline__ void cp16(uint32_t dst, const void* src) {
    asm volatile("cp.async.cg.shared.global [%0], [%1], 16;" :: "r"(dst), "l"(src));
}
#define CP_COMMIT() asm volatile("cp.async.commit_group;" ::: "memory")
#define CP_WAIT0()  asm volatile("cp.async.wait_group 0;" ::: "memory")
#define CP_WAIT1()  asm volatile("cp.async.wait_group 1;" ::: "memory")

__device__ __forceinline__ void ldsm_x4(uint32_t* r, uint32_t a) {
    asm volatile("ldmatrix.sync.aligned.m8n8.x4.shared.b16 {%0,%1,%2,%3}, [%4];"
                 : "=r"(r[0]), "=r"(r[1]), "=r"(r[2]), "=r"(r[3]) : "r"(a));
}
__device__ __forceinline__ void ldsm_x4t(uint32_t* r, uint32_t a) {
    asm volatile("ldmatrix.sync.aligned.m8n8.x4.trans.shared.b16 {%0,%1,%2,%3}, [%4];"
                 : "=r"(r[0]), "=r"(r[1]), "=r"(r[2]), "=r"(r[3]) : "r"(a));
}
__device__ __forceinline__ void mma16816(float* c, const uint32_t* a, uint32_t b0, uint32_t b1) {
    asm volatile("mma.sync.aligned.m16n8k16.row.col.f32.f16.f16.f32 "
                 "{%0,%1,%2,%3}, {%4,%5,%6,%7}, {%8,%9}, {%0,%1,%2,%3};"
                 : "+f"(c[0]), "+f"(c[1]), "+f"(c[2]), "+f"(c[3])
                 : "r"(a[0]), "r"(a[1]), "r"(a[2]), "r"(a[3]), "r"(b0), "r"(b1));
}
__device__ __forceinline__ float ex2(float x) {
    float r; asm("ex2.approx.f32 %0, %1;" : "=f"(r) : "f"(x)); return r;
}
__device__ __forceinline__ uint32_t h2bits(__half2 h) { return *(uint32_t*)&h; }
__device__ __forceinline__ uint32_t swzo(int row, int colb) {
    return (uint32_t)((row * 128 + colb) ^ ((row & 7) << 4));
}

// ---------------- merged prepass (unchanged) ----------------
__global__ void prepass_kernel(const int4* __restrict__ adj,
                               const float4* __restrict__ Q,
                               const float4* __restrict__ K,
                               const float4* __restrict__ V,
                               int N, int adjB)
{
    if (blockIdx.x < adjB) {
        const int g   = blockIdx.x * 256 + threadIdx.x;
        const int row = g >> 6, seg = g & 63;
        const int t   = seg >> 1, h = seg & 1;
        const int4* bp = adj + (size_t)row * (N >> 2) + t * 16 + h * 8;
        int4 a[8];
        #pragma unroll
        for (int i = 0; i < 8; i++) a[i] = bp[i];
        uint32_t w[4][4];
        #pragma unroll
        for (int i = 0; i < 4; i++) {
            int4 lo = a[2 * i], hi = a[2 * i + 1];
            w[0][i] = (lo.x > 0 ? 0xFFFFu : 0u) | (lo.y > 0 ? 0xFFFF0000u : 0u);
            w[1][i] = (lo.z > 0 ? 0xFFFFu : 0u) | (lo.w > 0 ? 0xFFFF0000u : 0u);
            w[2][i] = (hi.x > 0 ? 0xFFFFu : 0u) | (hi.y > 0 ? 0xFFFF0000u : 0u);
            w[3][i] = (hi.z > 0 ? 0xFFFFu : 0u) | (hi.w > 0 ? 0xFFFF0000u : 0u);
        }
        const int nT = N >> 6;
        #pragma unroll
        for (int qd = 0; qd < 4; qd++)
            ((uint4*)g_mask)[(((size_t)row * nT + t) * 4 + qd) * 2 + h] =
                make_uint4(w[qd][0], w[qd][1], w[qd][2], w[qd][3]);
        return;
    }
    __shared__ float skn[16];
    const int idx = (blockIdx.x - adjB) * 256 + threadIdx.x;
    float4 q = Q[idx], k = K[idx], v = V[idx];

    ((uint2*)g_qh)[idx] = make_uint2(h2bits(__floats2half2_rn(q.x, q.y)),
                                     h2bits(__floats2half2_rn(q.z, q.w)));
    const int rl  = idx >> 4;
    const int bh  = rl / N;
    const int row = rl - bh * N;
    const int t   = row >> 6, r = row & 63, c4 = idx & 15;
    const size_t u2 = ((size_t)(bh * (N >> 6) + t) * 128 + r) * 16 + c4;
    ((uint2*)g_kv)[u2]        = make_uint2(h2bits(__floats2half2_rn(k.x, k.y)),
                                           h2bits(__floats2half2_rn(k.z, k.w)));
    ((uint2*)g_kv)[u2 + 1024] = make_uint2(h2bits(__floats2half2_rn(v.x, v.y)),
                                           h2bits(__floats2half2_rn(v.z, v.w)));

    float qn2 = q.x * q.x + q.y * q.y + q.z * q.z + q.w * q.w;
    float kn2 = k.x * k.x + k.y * k.y + k.z * k.z + k.w * k.w;
    #pragma unroll
    for (int o = 8; o; o >>= 1) {
        qn2 += __shfl_xor_sync(0xffffffffu, qn2, o);
        kn2 += __shfl_xor_sync(0xffffffffu, kn2, o);
    }
    if ((threadIdx.x & 15) == 0) {
        g_qn2[idx >> 4] = qn2;
        skn[threadIdx.x >> 4] = kn2;
    }
    __syncthreads();
    if (threadIdx.x == 0) {
        float m = skn[0];
        #pragma unroll
        for (int i = 1; i < 16; i++) m = fmaxf(m, skn[i]);
        atomicMax((int*)&g_maxk2[bh], __float_as_int(m));
    }
}

// ---------------- main kernel: R11 layout + intra-tile pipelined epilogue ----------------
__global__ __launch_bounds__(TPB, 4)
void gat_hmma9_kernel(float* __restrict__ out, int N)
{
    extern __shared__ char sm[];
    const uint32_t smb = smem_u32(sm);

    const int tid  = threadIdx.x;
    const int wid  = tid >> 5;
    const int lane = tid & 31;
    const int mg   = lane >> 3;
    const int mr   = lane & 7;
    const int r4   = lane >> 2;
    const int qd   = lane & 3;

    const int bh   = blockIdx.y;
    const int row0 = blockIdx.x * BM;
    const int nT   = N / BN;

    // ---- Q fragments via stage0 ----
    {
        const char* qhB = (const char*)g_qh + ((size_t)bh * N + row0) * (DHD * 2);
        #pragma unroll
        for (int i = 0; i < 4; i++) {
            int idx = tid + i * TPB;
            int row = idx >> 3, c = idx & 7;
            cp16(smb + swzo(row, c * 16), qhB + row * 128 + c * 16);
        }
        CP_COMMIT(); CP_WAIT0();
        __syncthreads();
    }
    uint32_t qh[4][4];
    {
        const int arow = wid * 16 + ((mg & 1) << 3) + mr;
        #pragma unroll
        for (int kb = 0; kb < 4; kb++)
            ldsm_x4(qh[kb], smb + swzo(arow, kb * 32 + ((mg >> 1) << 4)));
    }
    __syncthreads();

    // ---- per-row bias, mask pointers, ones fragment ----
    const float mk2 = g_maxk2[bh];
    const int rowa = row0 + wid * 16 + r4;
    const float sb0 = 14.0f - sqrtf(g_qn2[(size_t)bh * N + rowa] * mk2) * K2E;
    const float sb1 = 14.0f - sqrtf(g_qn2[(size_t)bh * N + rowa + 8] * mk2) * K2E;
    const uint32_t* mpA = g_mask + (size_t)rowa * nT * 32 + qd * 8;
    const uint32_t* mpB = mpA + (size_t)8 * nT * 32;
    const uint32_t bo = (lane < 4) ? 0x3C003C00u : 0u;   // ones column B-fragment

    // ---- hoisted ldsm addresses ----
    const uint32_t mrx = (uint32_t)(mr << 4);
    uint32_t addrS[4], addrV[4];
    {
        uint32_t bS = smb + (uint32_t)((((mg >> 1) << 3) + mr) * 128);
        uint32_t bV = smb + 8192 + (uint32_t)((((mg & 1) << 3) + mr) * 128);
        #pragma unroll
        for (int k = 0; k < 4; k++) {
            addrS[k] = bS + ((uint32_t)(k * 32 + ((mg & 1) << 4)) ^ mrx);
            addrV[k] = bV + ((uint32_t)(k * 32 + ((mg >> 1) << 4)) ^ mrx);
        }
    }

    // ---- cp.async bases ----
    const uint32_t so0 = (uint32_t)((tid >> 3) * 128 + (((tid & 7) * 16) ^ (((tid >> 3) & 7) << 4)));
    const char* kvSrc = (const char*)g_kv + (size_t)bh * N * 256 + (tid >> 3) * 128 + (tid & 7) * 16;
    uint32_t cpDst = smb + STG + so0;
    int cpStage = 1;

    float o[8][4];
    #pragma unroll
    for (int i = 0; i < 8; i++)
        #pragma unroll
        for (int j = 0; j < 4; j++) o[i][j] = 0.f;
    float lfrag[4] = {0.f, 0.f, 0.f, 0.f};

    // prefetch tile 0 -> stage 0
    #pragma unroll
    for (int i = 0; i < 8; i++) cp16(smb + so0 + i * 2048, kvSrc + i * 2048);
    CP_COMMIT();
    kvSrc += 16384;

    int st = 0;
    for (int t = 0; t < nT; t++) {
        if (t + 1 < nT) {
            #pragma unroll
            for (int i = 0; i < 8; i++) cp16(cpDst + i * 2048, kvSrc + i * 2048);
            CP_COMMIT(); CP_WAIT1();
            kvSrc += 16384;
            int d2 = (cpStage == 2) ? -2 * STG : STG;
            cpStage = (cpStage == 2) ? 0 : cpStage + 1;
            cpDst += d2;
        } else {
            CP_WAIT0();
        }
        __syncthreads();   // single barrier per tile (3-stage ring)

        // hoisted mask loads (L2) — latency covered by first S-block MMAs
        const uint4 mq0 = *(const uint4*)(mpA);
        const uint4 mq1 = *(const uint4*)(mpA + 4);
        const uint4 mq2 = *(const uint4*)(mpB);
        const uint4 mq3 = *(const uint4*)(mpB + 4);
        mpA += 32; mpB += 32;
        const uint32_t mwA[8] = {mq0.x, mq0.y, mq0.z, mq0.w, mq1.x, mq1.y, mq1.z, mq1.w};
        const uint32_t mwB[8] = {mq2.x, mq2.y, mq2.z, mq2.w, mq3.x, mq3.y, mq3.z, mq3.w};

        // ---- 5-step pipeline: step j = S-MMAs(block j) + epilogue(block j-1) ----
        float cb[2][8];
        #pragma unroll
        for (int j = 0; j <= 4; j++) {
            if (j < 4) {
                float* cc = cb[j & 1];
                #pragma unroll
                for (int i = 0; i < 8; i++) cc[i] = 0.f;
                #pragma unroll
                for (int kb = 0; kb < 4; kb++) {
                    uint32_t bhr[4];
                    ldsm_x4(bhr, addrS[kb] + j * 2048);
                    mma16816(cc,     qh[kb], bhr[0], bhr[1]);
                    mma16816(cc + 4, qh[kb], bhr[2], bhr[3]);
                }
            }
            if (j > 0) {
                const int b = j - 1;
                const float* cc = cb[b & 1];
                float p0 = ex2(fmaf(cc[0], K2E, sb0));
                float p1 = ex2(fmaf(cc[1], K2E, sb0));
                float p2 = ex2(fmaf(cc[2], K2E, sb1));
                float p3 = ex2(fmaf(cc[3], K2E, sb1));
                float p4 = ex2(fmaf(cc[4], K2E, sb0));
                float p5 = ex2(fmaf(cc[5], K2E, sb0));
                float p6 = ex2(fmaf(cc[6], K2E, sb1));
                float p7 = ex2(fmaf(cc[7], K2E, sb1));
                uint32_t ph[4];
                ph[0] = h2bits(__floats2half2_rn(p0, p1)) & mwA[2 * b];
                ph[1] = h2bits(__floats2half2_rn(p2, p3)) & mwB[2 * b];
                ph[2] = h2bits(__floats2half2_rn(p4, p5)) & mwA[2 * b + 1];
                ph[3] = h2bits(__floats2half2_rn(p6, p7)) & mwB[2 * b + 1];
                #pragma unroll
                for (int jj = 0; jj < 4; jj++) {
                    uint32_t vh4[4];
                    ldsm_x4t(vh4, addrV[jj] + b * 2048);
                    mma16816(o[2 * jj],     ph, vh4[0], vh4[1]);
                    mma16816(o[2 * jj + 1], ph, vh4[2], vh4[3]);
                }
                mma16816(lfrag, ph, bo, bo);
            }
        }

        // rotate stage bases
        int d = (st == 2) ? -2 * STG : STG;
        st = (st == 2) ? 0 : st + 1;
        #pragma unroll
        for (int k = 0; k < 4; k++) { addrS[k] += d; addrV[k] += d; }
    }

    // ---- normalize + store (l lives in col 0 -> lanes with qd==0) ----
    float l0 = __shfl_sync(0xffffffffu, lfrag[0], lane & 28);
    float l1 = __shfl_sync(0xffffffffu, lfrag[2], lane & 28);
    const float inv0 = 1.0f / l0;
    const float inv1 = 1.0f / l1;

    const int orow = row0 + wid * 16 + r4;
    float2* op = (float2*)out;
    #pragma unroll
    for (int nb = 0; nb < 8; nb++) {
        const int d = nb * 8 + qd * 2;
        op[(((size_t)bh * N + orow) * DHD + d) >> 1] =
            make_float2(o[nb][0] * inv0, o[nb][1] * inv0);
        op[(((size_t)bh * N + orow + 8) * DHD + d) >> 1] =
            make_float2(o[nb][2] * inv1, o[nb][3] * inv1);
    }
}

// ---------------- launcher ----------------
extern "C" void kernel_launch(void* const* d_in, const int* in_sizes, int n_in,
                              void* d_out, int out_size)
{
    const float* Q   = (const float*)d_in[0];
    const float* K   = (const float*)d_in[1];
    const float* V   = (const float*)d_in[2];
    const int*   adj = (const int*)d_in[3];
    float*       out = (float*)d_out;

    const int N  = (int)(sqrt((double)in_sizes[3]) + 0.5);
    const int BH = in_sizes[0] / (N * DHD);

    const int adjB = (N * N / 32) / 256;
    const int cvtB = (BH * N * DHD / 4) / 256;
    prepass_kernel<<<adjB + cvtB, 256>>>((const int4*)adj, (const float4*)Q,
                                         (const float4*)K, (const float4*)V, N, adjB);

    cudaFuncSetAttribute(gat_hmma9_kernel,
                         cudaFuncAttributeMaxDynamicSharedMemorySize, SMEM_TOTAL);
    dim3 grid(N / BM, BH);
    gat_hmma9_kernel<<<grid, TPB, SMEM_TOTAL>>>(out, N);
}